// round 1
// baseline (speedup 1.0000x reference)
#include <cuda_runtime.h>
#include <cstdint>
#include <cstddef>

// Problem dims (fixed for this problem)
#define BATCH 512
#define ICAPS 1152
#define DDIM  8
#define JCAPS 10
#define CDIM  16

// Kernel config
#define TPB          384          // 12 warps; thread = (i-row, c-quad)
#define ROWS_PER_RD  96           // rows of W staged per round (TPB/4)
#define NRD          12           // 1152 / 96
#define RSTRIDE      144          // floats per smem W row: 128 + 16 pad (576B; 576 mod 128 = 64 -> conflict-free phases)
#define WBUF_FLOATS  (ROWS_PER_RD * RSTRIDE)   // 13824 floats per buffer

// Shared memory layout (in floats)
#define OFF_WBUF 0
#define OFF_BL   (2 * WBUF_FLOATS)             // 27648 : routing logits b[2][1152]
#define OFF_RED  (OFF_BL + 2 * ICAPS)          // 29952 : per-(warp,q) partials 48 x 12
#define OFF_TOT  (OFF_RED + 48 * 12)           // 30528 : reduced totals (34)
#define OFF_V    (OFF_TOT + 36)                // 30564 : v[2][16]
#define SMEM_FLOATS (OFF_V + 32)               // 30596 floats = 122384 B

__device__ __forceinline__ void cp16(float* dst, const float* src) {
    unsigned s = (unsigned)__cvta_generic_to_shared(dst);
    asm volatile("cp.async.cg.shared.global [%0], [%1], 16;" :: "r"(s), "l"(src));
}

__global__ void __launch_bounds__(TPB, 1)
digitcaps_kernel(const float* __restrict__ x,
                 const float* __restrict__ W,
                 float* __restrict__ out)
{
    extern __shared__ float sm[];

    const int tid  = threadIdx.x;
    const int j    = blockIdx.x % JCAPS;
    const int bp   = blockIdx.x / JCAPS;      // batch pair index, 0..255
    const int b0   = bp * 2;
    const int b1   = bp * 2 + 1;
    const int q    = tid & 3;                 // c-quad: channels q*4 .. q*4+3
    const int rrow = tid >> 2;                // row-in-round: 0..95
    const int lane = tid & 31;
    const int warp = tid >> 5;

    // Zero logits and v
    for (int k = tid; k < 2 * ICAPS; k += TPB) sm[OFF_BL + k] = 0.f;
    if (tid < 32) sm[OFF_V + tid] = 0.f;

    const float* Wj = W + (size_t)j * ICAPS * (DDIM * CDIM);

    // Register-resident x_hat for both batches: [round][4 channels]
    float xh0[NRD][4];
    float xh1[NRD][4];

    // ---- Stage round 0 ----
    {
        float* dst = sm + OFF_WBUF;
        #pragma unroll
        for (int wv = 0; wv < 8; wv++) {
            int idx = wv * TPB + tid;            // 0..3071 float4-chunks
            int row = idx >> 5, ch = idx & 31;
            cp16(dst + row * RSTRIDE + ch * 4, Wj + (size_t)idx * 4);
        }
        asm volatile("cp.async.commit_group;");
    }

    // ---- Build phase: pipelined over 12 rounds ----
    #pragma unroll
    for (int rd = 0; rd < NRD; rd++) {
        if (rd + 1 < NRD) {
            const float* src = Wj + (size_t)(rd + 1) * ROWS_PER_RD * (DDIM * CDIM);
            float* dst = sm + OFF_WBUF + ((rd + 1) & 1) * WBUF_FLOATS;
            #pragma unroll
            for (int wv = 0; wv < 8; wv++) {
                int idx = wv * TPB + tid;
                int row = idx >> 5, ch = idx & 31;
                cp16(dst + row * RSTRIDE + ch * 4, src + (size_t)idx * 4);
            }
            asm volatile("cp.async.commit_group;");
            asm volatile("cp.async.wait_group 1;");
        } else {
            asm volatile("cp.async.wait_group 0;");
        }
        __syncthreads();

        const int i = rd * ROWS_PER_RD + rrow;
        const float* wb = sm + OFF_WBUF + (rd & 1) * WBUF_FLOATS + rrow * RSTRIDE + q * 4;

        float xr0[8], xr1[8];
        {
            const float4* p0 = reinterpret_cast<const float4*>(x + ((size_t)b0 * ICAPS + i) * DDIM);
            const float4* p1 = reinterpret_cast<const float4*>(x + ((size_t)b1 * ICAPS + i) * DDIM);
            float4 a = p0[0], b = p0[1];
            xr0[0]=a.x; xr0[1]=a.y; xr0[2]=a.z; xr0[3]=a.w;
            xr0[4]=b.x; xr0[5]=b.y; xr0[6]=b.z; xr0[7]=b.w;
            float4 c = p1[0], d = p1[1];
            xr1[0]=c.x; xr1[1]=c.y; xr1[2]=c.z; xr1[3]=c.w;
            xr1[4]=d.x; xr1[5]=d.y; xr1[6]=d.z; xr1[7]=d.w;
        }

        float a00=0.f,a01=0.f,a02=0.f,a03=0.f;
        float a10=0.f,a11=0.f,a12=0.f,a13=0.f;
        #pragma unroll
        for (int d = 0; d < 8; d++) {
            float4 w4 = *reinterpret_cast<const float4*>(wb + d * CDIM);
            a00 = fmaf(xr0[d], w4.x, a00);
            a01 = fmaf(xr0[d], w4.y, a01);
            a02 = fmaf(xr0[d], w4.z, a02);
            a03 = fmaf(xr0[d], w4.w, a03);
            a10 = fmaf(xr1[d], w4.x, a10);
            a11 = fmaf(xr1[d], w4.y, a11);
            a12 = fmaf(xr1[d], w4.z, a12);
            a13 = fmaf(xr1[d], w4.w, a13);
        }
        xh0[rd][0]=a00; xh0[rd][1]=a01; xh0[rd][2]=a02; xh0[rd][3]=a03;
        xh1[rd][0]=a10; xh1[rd][1]=a11; xh1[rd][2]=a12; xh1[rd][3]=a13;

        __syncthreads();   // protect buffer (rd&1) before it is restaged next iter
    }

    // ---- Routing: 3 iterations, all on-chip ----
    float* blp0 = sm + OFF_BL;
    float* blp1 = sm + OFF_BL + ICAPS;
    float* red  = sm + OFF_RED;
    float* tot  = sm + OFF_TOT;
    float* vsm  = sm + OFF_V;

    #pragma unroll
    for (int it = 0; it < 3; it++) {
        float vq0[4], vq1[4];
        #pragma unroll
        for (int c = 0; c < 4; c++) {
            vq0[c] = vsm[q * 4 + c];
            vq1[c] = vsm[16 + q * 4 + c];
        }

        float Sp0[4] = {0.f,0.f,0.f,0.f};
        float Sp1[4] = {0.f,0.f,0.f,0.f};
        float Zp0 = 0.f, Zp1 = 0.f;

        #pragma unroll
        for (int rd = 0; rd < NRD; rd++) {
            const int i = rd * ROWS_PER_RD + rrow;
            // agreement a = v . x_hat_i  (partial over this thread's 4 channels)
            float a0 = vq0[0]*xh0[rd][0] + vq0[1]*xh0[rd][1] + vq0[2]*xh0[rd][2] + vq0[3]*xh0[rd][3];
            float a1 = vq1[0]*xh1[rd][0] + vq1[1]*xh1[rd][1] + vq1[2]*xh1[rd][2] + vq1[3]*xh1[rd][3];
            // reduce across the 4 c-quad lanes (lanes differing in bits 0..1)
            a0 += __shfl_xor_sync(0xffffffffu, a0, 1);
            a0 += __shfl_xor_sync(0xffffffffu, a0, 2);
            a1 += __shfl_xor_sync(0xffffffffu, a1, 1);
            a1 += __shfl_xor_sync(0xffffffffu, a1, 2);

            float nb0 = blp0[i] + a0;   // first iter: v=0 -> a=0 -> b=0 -> e=1 (uniform softmax)
            float nb1 = blp1[i] + a1;
            if (q == 0) { blp0[i] = nb0; blp1[i] = nb1; }

            // un-normalized softmax weights (|b| <= ~1.5, no max-subtraction needed)
            float e0 = __expf(nb0);
            float e1 = __expf(nb1);
            Zp0 += e0; Zp1 += e1;
            #pragma unroll
            for (int c = 0; c < 4; c++) {
                Sp0[c] = fmaf(e0, xh0[rd][c], Sp0[c]);
                Sp1[c] = fmaf(e1, xh1[rd][c], Sp1[c]);
            }
        }

        // Warp reduce over same-q lanes (masks 4,8,16 -> 8 rows per warp)
        #pragma unroll
        for (int m = 4; m < 32; m <<= 1) {
            #pragma unroll
            for (int c = 0; c < 4; c++) {
                Sp0[c] += __shfl_xor_sync(0xffffffffu, Sp0[c], m);
                Sp1[c] += __shfl_xor_sync(0xffffffffu, Sp1[c], m);
            }
            Zp0 += __shfl_xor_sync(0xffffffffu, Zp0, m);
            Zp1 += __shfl_xor_sync(0xffffffffu, Zp1, m);
        }
        if (lane < 4) {   // lane == its q class
            float* r = red + (warp * 4 + lane) * 12;
            r[0]=Sp0[0]; r[1]=Sp0[1]; r[2]=Sp0[2]; r[3]=Sp0[3]; r[4]=Zp0;
            r[5]=Sp1[0]; r[6]=Sp1[1]; r[7]=Sp1[2]; r[8]=Sp1[3]; r[9]=Zp1;
        }
        __syncthreads();

        // Final cross-warp reduction
        if (tid < 32) {
            const int b  = tid >> 4;
            const int c  = tid & 15;
            const int qq = c >> 2;
            const int jj = c & 3;
            float s = 0.f;
            #pragma unroll
            for (int w2 = 0; w2 < 12; w2++)
                s += red[(w2 * 4 + qq) * 12 + b * 5 + jj];
            tot[tid] = s;
        } else if (tid < 34) {
            const int b = tid - 32;
            // Z lives (non-duplicated) in q==0 entries only
            float z = 0.f;
            #pragma unroll
            for (int w2 = 0; w2 < 12; w2++)
                z += red[(w2 * 4) * 12 + b * 5 + 4];
            tot[32 + b] = z;
        }
        __syncthreads();

        // squash (thread 0), broadcast v via smem
        if (tid == 0) {
            #pragma unroll
            for (int b = 0; b < 2; b++) {
                float inv = 1.f / tot[32 + b];
                float sv[16];
                float n2 = 0.f;
                #pragma unroll
                for (int c = 0; c < 16; c++) {
                    sv[c] = tot[b * 16 + c] * inv;
                    n2 += sv[c] * sv[c];
                }
                float nr = sqrtf(n2);
                float coef = (n2 / (1.f + n2)) / (nr + 1e-7f);
                #pragma unroll
                for (int c = 0; c < 16; c++)
                    vsm[b * 16 + c] = coef * sv[c];
            }
        }
        __syncthreads();
    }

    // ---- Output v3: (B, J, C) row-major ----
    if (tid < 32) {
        const int b = tid >> 4;
        const int c = tid & 15;
        out[((size_t)(bp * 2 + b) * JCAPS + j) * CDIM + c] = vsm[b * 16 + c];
    }
}

extern "C" void kernel_launch(void* const* d_in, const int* in_sizes, int n_in,
                              void* d_out, int out_size)
{
    const float* x = (const float*)d_in[0];
    const float* W = (const float*)d_in[1];
    // Defensive: swap if metadata order is (W, x)
    if (n_in >= 2 &&
        in_sizes[0] == JCAPS * ICAPS * DDIM * CDIM &&
        in_sizes[1] == BATCH * ICAPS * DDIM) {
        const float* t = x; x = W; W = t;
    }
    float* out = (float*)d_out;

    cudaFuncSetAttribute(digitcaps_kernel,
                         cudaFuncAttributeMaxDynamicSharedMemorySize,
                         SMEM_FLOATS * (int)sizeof(float));

    dim3 grid((BATCH / 2) * JCAPS);   // 2560 CTAs: one per (j, batch-pair)
    digitcaps_kernel<<<grid, TPB, SMEM_FLOATS * sizeof(float)>>>(x, W, out);
}